// round 12
// baseline (speedup 1.0000x reference)
#include <cuda_runtime.h>
#include <cuda_bf16.h>
#include <cstdint>

#define S_LEN  262144
#define NDIM   128
#define TILE   64
#define NTILES 4096
#define NCTA   296        // 2 CTAs/SM x 148 SMs (all co-resident)
#define NPROD  128        // producer CTAs for W

// ---------------- device scratch ----------------
__device__ __align__(16) __nv_bfloat16 g_Bsw[NDIM * NDIM];  // B[t][k]=bf16(M[k][t]), swizzled
__device__ float g_partials[NCTA];
__device__ float g_l1part[NPROD];
__device__ int   g_done;       // producer counter (reset by last CTA)
__device__ int   g_ticket;     // completion ticket (reset by last CTA)

// ---------------- smem byte offsets (per CTA 101376 B -> 2 CTAs/SM) ----------------
#define STG0  0          // fp32 staging buf0: 64 x 512B = 32768
#define STG1  32768      // buf1
#define BOF   65536      // B bf16 swizzled: 32768
#define NXT   98304      // boundary rows fp32: 2 slots x 512
#define RED   99328      // reduction: 256 doubles = 2048 (aliases producer l1 floats)
#define SMEM_BYTES 101376

// ---------------- helpers ----------------
__device__ __forceinline__ uint32_t smem_u32(const void* p) {
    uint32_t a;
    asm("{ .reg .u64 t; cvta.to.shared.u64 t, %1; cvt.u32.u64 %0, t; }" : "=r"(a) : "l"(p));
    return a;
}
__device__ __forceinline__ uint32_t bf2(float xh, float xl) {
    uint32_t r;
    asm("cvt.rn.bf16x2.f32 %0, %1, %2;" : "=r"(r) : "f"(xh), "f"(xl));
    return r;
}
__device__ __forceinline__ float4 lds128f(uint32_t a) {
    float4 v;
    asm volatile("ld.shared.v4.f32 {%0,%1,%2,%3}, [%4];"
                 : "=f"(v.x), "=f"(v.y), "=f"(v.z), "=f"(v.w) : "r"(a));
    return v;
}
__device__ __forceinline__ float2 lds64f(uint32_t a) {
    float2 v;
    asm volatile("ld.shared.v2.f32 {%0,%1}, [%2];" : "=f"(v.x), "=f"(v.y) : "r"(a));
    return v;
}
__device__ __forceinline__ uint2 lds64u(uint32_t a) {
    uint2 v;
    asm volatile("ld.shared.v2.b32 {%0,%1}, [%2];" : "=r"(v.x), "=r"(v.y) : "r"(a));
    return v;
}
__device__ __forceinline__ void cpa16(uint32_t dst, const void* src) {
    asm volatile("cp.async.cg.shared.global [%0], [%1], 16;" :: "r"(dst), "l"(src));
}
__device__ __forceinline__ void cpa_commit() { asm volatile("cp.async.commit_group;" ::: "memory"); }
__device__ __forceinline__ void cpa_wait0()  { asm volatile("cp.async.wait_group 0;" ::: "memory"); }

__device__ __forceinline__ void mma_bf16(float* d, const uint32_t* a, uint32_t b0, uint32_t b1) {
    asm volatile(
        "mma.sync.aligned.m16n8k16.row.col.f32.bf16.bf16.f32 "
        "{%0,%1,%2,%3}, {%4,%5,%6,%7}, {%8,%9}, {%0,%1,%2,%3};"
        : "+f"(d[0]), "+f"(d[1]), "+f"(d[2]), "+f"(d[3])
        : "r"(a[0]), "r"(a[1]), "r"(a[2]), "r"(a[3]), "r"(b0), "r"(b1));
}
__device__ __forceinline__ float softplusf(float x) {
    const float l = __logf(1.0f + __expf(x));
    return (x > 15.0f) ? x : l;
}
// swizzled byte offset: B plane row t (256B rows), element index k
__device__ __forceinline__ uint32_t gsw(int t, int k) {
    return (uint32_t)(t * 256 + (((k >> 2) ^ ((t & 7) << 2)) << 3) + (k & 3) * 2);
}

// ---------------- fused persistent kernel ----------------
extern __shared__ char dsm[];

__device__ __forceinline__ void issue_prefetch(const float* __restrict__ In, int tile,
                                               uint32_t sb, int slot, int tid) {
    const char* src = (const char*)(In + (size_t)tile * TILE * NDIM);
    const uint32_t stg = sb + (slot ? STG1 : STG0);
#pragma unroll
    for (int j = 0; j < 8; ++j) {
        const int idx = tid + 256 * j;           // 2048 16B chunks (64 rows x 512B)
        const int r = idx >> 5, c = idx & 31;
        cpa16(stg + r * 512 + ((c ^ ((r & 1) << 2)) << 4), src + r * 512 + c * 16);
    }
    if (tid < 32) {
        size_t nr = (size_t)tile * TILE + TILE;   // boundary row
        if (nr >= S_LEN) nr = 0;                   // clamped; masked in epilogue
        cpa16(sb + NXT + slot * 512 + tid * 16, (const char*)(In + nr * NDIM) + tid * 16);
    }
    cpa_commit();
}

__global__ void __launch_bounds__(256, 2)
fused_kernel(const float* __restrict__ In, const float* __restrict__ WQ,
             const float* __restrict__ WK, float* __restrict__ out) {
    const uint32_t sb = smem_u32(dsm);
    const int tid  = threadIdx.x;
    const int lane = tid & 31;
    const int w    = tid >> 5;
    const int m0   = (w & 3) << 4;     // warp tile: 16m x 64n (grid 4m x 2n)
    const int n0   = (w >> 2) << 6;
    const int g    = lane >> 2;
    const int q    = lane & 3;
    const int bx   = blockIdx.x;

    // first tile prefetch ASAP (async; overlaps producer phase)
    issue_prefetch(In, bx, sb, 0, tid);

    // ---- producers: CTA c < NPROD computes column c of M -> B row + l1 partial ----
    if (bx < NPROD) {
        const int c  = bx;
        const int i  = tid >> 1;      // M row index (k)
        const int jh = tid & 1;
        float acc = 0.f;
#pragma unroll 8
        for (int jj = 0; jj < 64; ++jj) {
            const int j = jh * 64 + jj;
            acc = fmaf(__ldg(WK + j * NDIM + i), __ldg(WQ + j * NDIM + c), acc);
        }
        acc += __shfl_xor_sync(0xffffffffu, acc, 1);
        float* sL1 = (float*)(dsm + RED);
        if (jh == 0) {
            *(__nv_bfloat16*)((char*)g_Bsw + gsw(c, i)) = __float2bfloat16(acc);
            sL1[i] = 1.0f / (1.0f + __expf(-acc));      // sigmoid(M[i][c])
        }
        __syncthreads();
        for (int o = 64; o; o >>= 1) {              // deterministic tree
            if (tid < o) sL1[tid] += sL1[tid + o];
            __syncthreads();
        }
        if (tid == 0) g_l1part[c] = sL1[0];
        __threadfence();
        __syncthreads();
        if (tid == 0) atomicAdd(&g_done, 1);
    }

    // ---- wait for all producers, stage B ----
    if (tid == 0) {
        int v;
        do {
            asm volatile("ld.acquire.gpu.b32 %0, [%1];" : "=r"(v) : "l"(&g_done) : "memory");
            if (v < NPROD) __nanosleep(64);
        } while (v < NPROD);
    }
    __syncthreads();
    {
        const float4* src = (const float4*)g_Bsw;
        float4* dst = (float4*)(dsm + BOF);
#pragma unroll
        for (int k = tid; k < 2048; k += 256) dst[k] = src[k];
    }

    const int rA0 = m0 + g;
    const uint32_t xA = (uint32_t)((g & 1) << 2);
    const uint32_t xB = (uint32_t)(g << 2);
    const uint32_t bB = sb + BOF + (uint32_t)(n0 + g) * 256;
    const uint32_t xN = (uint32_t)(((g + 1) & 1) << 2);   // row parity of rA+1 / rB+1

    const int nt = (NTILES - bx + NCTA - 1) / NCTA;
    float loss = 0.f;

    for (int i = 0; i < nt; ++i) {
        const int tile = bx + i * NCTA;
        const uint32_t stg = sb + ((i & 1) ? STG1 : STG0);
        const uint32_t bA = stg + (uint32_t)rA0 * 512;

        cpa_wait0();                     // buf(i&1) landed
        __syncthreads();                 // visible to all; prev tile done with buf((i+1)&1)
        if (i + 1 < nt)                  // fetch next tile NOW -> overlaps this tile's compute
            issue_prefetch(In, bx + (i + 1) * NCTA, sb, (i + 1) & 1, tid);

        // -------- mainloop --------
        float dacc[8][4];
#pragma unroll
        for (int nf = 0; nf < 8; ++nf)
#pragma unroll
            for (int j = 0; j < 4; ++j) dacc[nf][j] = 0.f;
        float rsum[2] = {0.f, 0.f};

#pragma unroll
        for (int ks = 0; ks < 8; ++ks) {
            const uint32_t c = (uint32_t)(4 * ks + q);
            const uint32_t offA = ((c ^ xA) << 4);
            const float4 v0 = lds128f(bA + offA);               // row rA0
            const float4 v1 = lds128f(bA + 8 * 512 + offA);     // row rA0+8
            rsum[0] += (v0.x + v0.y) + (v0.z + v0.w);
            rsum[1] += (v1.x + v1.y) + (v1.z + v1.w);
            uint32_t a0[4];
            a0[0] = bf2(v0.y, v0.x); a0[1] = bf2(v1.y, v1.x);
            a0[2] = bf2(v0.w, v0.z); a0[3] = bf2(v1.w, v1.z);
            const uint32_t offB = ((c ^ xB) << 3);
#pragma unroll
            for (int nf = 0; nf < 8; ++nf) {
                const uint2 b = lds64u(bB + (uint32_t)nf * 2048 + offB);
                mma_bf16(dacc[nf], a0, b.x, b.y);
            }
        }

        // quad-reduce rowsums
#pragma unroll
        for (int j = 0; j < 2; ++j) {
            rsum[j] += __shfl_xor_sync(0xffffffffu, rsum[j], 1);
            rsum[j] += __shfl_xor_sync(0xffffffffu, rsum[j], 2);
        }

        // -------- epilogue (targets from this tile's staging) --------
        const size_t base = (size_t)tile * TILE;
        const int rA = rA0;                    // <= 55 (target rA+1 in-tile)
        const int rB = rA + 8;                 // <= 63 (target rB+1 may be boundary)
        const float rsA = rsum[0];
        const float rsB = rsum[1];
        const bool vB = (base + rB) < (size_t)(S_LEN - 1);
#pragma unroll
        for (int nf = 0; nf < 8; ++nf) {
            const int col0 = n0 + 8 * nf + 2 * q;
            const uint32_t off = (((uint32_t)(col0 >> 2) ^ xN) << 4) + ((col0 & 3) << 2);
            const float2 nxa = lds64f(stg + (uint32_t)(rA + 1) * 512 + off);
            const float2 nxb = (rB < TILE - 1)
                                   ? lds64f(stg + (uint32_t)(rB + 1) * 512 + off)
                                   : lds64f(sb + NXT + (uint32_t)(i & 1) * 512 + col0 * 4);
            const float* d = dacc[nf];
            const float t0 = fmaf(softplusf(d[0]), rsA, -nxa.x);
            const float t1 = fmaf(softplusf(d[1]), rsA, -nxa.y);
            loss = fmaf(t0, t0, loss);
            loss = fmaf(t1, t1, loss);
            if (vB) {
                const float t2 = fmaf(softplusf(d[2]), rsB, -nxb.x);
                const float t3 = fmaf(softplusf(d[3]), rsB, -nxb.y);
                loss = fmaf(t2, t2, loss);
                loss = fmaf(t3, t3, loss);
            }
        }
    }

    // ---- deterministic CTA reduction ----
    float* sRed = (float*)(dsm + RED);
    __syncthreads();
    sRed[tid] = loss;
    __syncthreads();
#pragma unroll
    for (int o = 128; o; o >>= 1) {
        if (tid < o) sRed[tid] += sRed[tid + o];
        __syncthreads();
    }
    if (tid == 0) g_partials[bx] = sRed[0];

    // ---- last-CTA final reduce (fixed-order => deterministic) ----
    __shared__ int sLast;
    if (tid == 0) {
        __threadfence();
        sLast = (atomicAdd(&g_ticket, 1) == NCTA - 1);
    }
    __syncthreads();
    if (sLast) {
        __threadfence();
        double* dRed = (double*)(dsm + RED);
        double s = 0.0;
        for (int k = tid; k < NCTA; k += 256) s += (double)__ldcg(&g_partials[k]);
        dRed[tid] = s;
        __syncthreads();
        for (int o = 128; o; o >>= 1) {
            if (tid < o) dRed[tid] += dRed[tid + o];
            __syncthreads();
        }
        if (tid == 0)
            out[0] = (float)(dRed[0] / ((double)(S_LEN - 1) * (double)NDIM));
        __syncthreads();

        dRed[tid] = (tid < NPROD) ? (double)__ldcg(&g_l1part[tid]) : 0.0;
        __syncthreads();
        for (int o = 128; o; o >>= 1) {
            if (tid < o) dRed[tid] += dRed[tid + o];
            __syncthreads();
        }
        if (tid == 0) {
            out[1] = (float)dRed[0];
            g_done = 0;                  // reset for next graph replay
            g_ticket = 0;
        }
    }
}

// ---------------- launch ----------------
extern "C" void kernel_launch(void* const* d_in, const int* in_sizes, int n_in,
                              void* d_out, int out_size) {
    const float* In = (const float*)d_in[0];
    const float* WQ = (const float*)d_in[1];
    const float* WK = (const float*)d_in[2];
    float* out = (float*)d_out;

    cudaFuncSetAttribute(fused_kernel,
                         cudaFuncAttributeMaxDynamicSharedMemorySize, SMEM_BYTES);
    fused_kernel<<<NCTA, 256, SMEM_BYTES>>>(In, WQ, WK, out);
}

// round 13
// speedup vs baseline: 1.3896x; 1.3896x over previous
#include <cuda_runtime.h>
#include <cuda_bf16.h>
#include <cstdint>

#define S_LEN  262144
#define NDIM   128
#define TILE   128
#define NTILES 2048
#define NCTA   296        // 2 CTAs/SM x 148 SMs (all co-resident)
#define NPROD  128        // producer CTAs for W

// ---------------- device scratch ----------------
__device__ __align__(16) __nv_bfloat16 g_Bsw[NDIM * NDIM];  // B[t][k]=bf16(M[k][t]), swizzled
__device__ float g_partials[NCTA];
__device__ float g_l1part[NPROD];
__device__ int   g_done;       // producer counter (reset by last CTA)
__device__ int   g_ticket;     // completion ticket (reset by last CTA)

// ---------------- smem byte offsets (per CTA 102400 B -> 2 CTAs/SM) ----------------
#define PLN0  0          // bf16 A plane buf0: 128 x 256B = 32768 (swizzled)
#define PLN1  32768      // buf1
#define BOF   65536      // B bf16 swizzled: 32768
#define NXT   98304      // boundary rows fp32: 2 slots x 512
#define ROWS  99328      // rowsums fp32: 2 slots x 128
#define RED   100352     // reduction: 256 doubles = 2048 (aliases producer l1 floats)
#define SMEM_BYTES 102400

// ---------------- helpers ----------------
__device__ __forceinline__ uint32_t smem_u32(const void* p) {
    uint32_t a;
    asm("{ .reg .u64 t; cvta.to.shared.u64 t, %1; cvt.u32.u64 %0, t; }" : "=r"(a) : "l"(p));
    return a;
}
__device__ __forceinline__ uint32_t bf2(float xh, float xl) {
    uint32_t r;
    asm("cvt.rn.bf16x2.f32 %0, %1, %2;" : "=r"(r) : "f"(xh), "f"(xl));
    return r;
}
__device__ __forceinline__ float lo_f(uint32_t p) { return __uint_as_float(p << 16); }
__device__ __forceinline__ float hi_f(uint32_t p) { return __uint_as_float(p & 0xffff0000u); }

__device__ __forceinline__ float2 lds64f(uint32_t a) {
    float2 v;
    asm volatile("ld.shared.v2.f32 {%0,%1}, [%2];" : "=f"(v.x), "=f"(v.y) : "r"(a));
    return v;
}
__device__ __forceinline__ uint2 lds64u(uint32_t a) {
    uint2 v;
    asm volatile("ld.shared.v2.b32 {%0,%1}, [%2];" : "=r"(v.x), "=r"(v.y) : "r"(a));
    return v;
}
__device__ __forceinline__ uint32_t lds32(uint32_t a) {
    uint32_t v;
    asm volatile("ld.shared.b32 %0, [%1];" : "=r"(v) : "r"(a));
    return v;
}
__device__ __forceinline__ void sts64(uint32_t a, uint64_t v) {
    asm volatile("st.shared.b64 [%0], %1;" :: "r"(a), "l"(v));
}
__device__ __forceinline__ void mma_bf16(float* d, const uint32_t* a, uint32_t b0, uint32_t b1) {
    asm volatile(
        "mma.sync.aligned.m16n8k16.row.col.f32.bf16.bf16.f32 "
        "{%0,%1,%2,%3}, {%4,%5,%6,%7}, {%8,%9}, {%0,%1,%2,%3};"
        : "+f"(d[0]), "+f"(d[1]), "+f"(d[2]), "+f"(d[3])
        : "r"(a[0]), "r"(a[1]), "r"(a[2]), "r"(a[3]), "r"(b0), "r"(b1));
}
__device__ __forceinline__ float softplusf(float x) {
    const float l = __logf(1.0f + __expf(x));
    return (x > 15.0f) ? x : l;
}
// swizzled byte offset in a bf16 plane (256B rows): row r, element index k
__device__ __forceinline__ uint32_t gsw(int r, int k) {
    return (uint32_t)(r * 256 + (((k >> 2) ^ ((r & 7) << 2)) << 3) + (k & 3) * 2);
}

// ---------------- fused persistent kernel ----------------
extern __shared__ char dsm[];

// LDG fp32 -> fp32 rowsums + bf16 plane (swizzled) + boundary row
__device__ __forceinline__ void ldg_pass(const float* __restrict__ In, int tile,
                                         int slot, uint32_t sb, int tid) {
    const int lane = tid & 31;
    const int w    = tid >> 5;
    const int p    = lane >> 3;          // row-in-group 0..3
    const int cc   = lane & 7;           // chunk base 0..7
    const uint32_t pln = sb + (slot ? PLN1 : PLN0);
    float* sRow = (float*)(dsm + ROWS) + slot * 128;
    const float4* src = (const float4*)(In + (size_t)tile * TILE * NDIM);
#pragma unroll
    for (int jr = 0; jr < 4; ++jr) {
        const int r = 16 * w + 4 * jr + p;
        const uint32_t xr = (uint32_t)((r & 7) << 2);
        const uint32_t rbase = pln + (uint32_t)r * 256;
        float rs = 0.f;
#pragma unroll
        for (int j = 0; j < 4; ++j) {
            const int c = cc + 8 * j;                   // float4 chunk 0..31
            const float4 v = __ldcs(&src[r * 32 + c]);
            rs += (v.x + v.y) + (v.z + v.w);
            const uint32_t lo = bf2(v.y, v.x);
            const uint32_t hi = bf2(v.w, v.z);
            sts64(rbase + (((uint32_t)c ^ xr) << 3), ((uint64_t)hi << 32) | lo);
        }
        rs += __shfl_xor_sync(0xffffffffu, rs, 1);
        rs += __shfl_xor_sync(0xffffffffu, rs, 2);
        rs += __shfl_xor_sync(0xffffffffu, rs, 4);
        if (cc == 0) sRow[r] = rs;
    }
    if (tid < 32) {   // boundary row = first row of sequentially-next block
        size_t nr = (size_t)tile * TILE + TILE;
        if (nr >= S_LEN) nr = 0;                        // clamped; masked in epilogue
        const float4 v = __ldg((const float4*)(In + nr * NDIM) + tid);
        ((float4*)(dsm + NXT))[slot * 32 + tid] = v;
    }
}

__global__ void __launch_bounds__(256, 2)
fused_kernel(const float* __restrict__ In, const float* __restrict__ WQ,
             const float* __restrict__ WK, float* __restrict__ out) {
    const uint32_t sb = smem_u32(dsm);
    const int tid  = threadIdx.x;
    const int lane = tid & 31;
    const int w    = tid >> 5;
    const int m0   = (w & 3) << 5;     // warp tile: 32m x 64n (grid 4m x 2n)
    const int n0   = (w >> 2) << 6;
    const int g    = lane >> 2;
    const int q    = lane & 3;
    const int bx   = blockIdx.x;

    // ---- producers: CTA c < NPROD computes column c of M -> B row + l1 partial ----
    if (bx < NPROD) {
        const int c  = bx;
        const int i  = tid >> 1;      // M row index (k)
        const int jh = tid & 1;
        float acc = 0.f;
#pragma unroll 8
        for (int jj = 0; jj < 64; ++jj) {
            const int j = jh * 64 + jj;
            acc = fmaf(__ldg(WK + j * NDIM + i), __ldg(WQ + j * NDIM + c), acc);
        }
        acc += __shfl_xor_sync(0xffffffffu, acc, 1);
        float* sL1 = (float*)(dsm + RED);
        if (jh == 0) {
            *(__nv_bfloat16*)((char*)g_Bsw + gsw(c, i)) = __float2bfloat16(acc);
            sL1[i] = 1.0f / (1.0f + __expf(-acc));      // sigmoid(M[i][c])
        }
        __syncthreads();
        for (int o = 64; o; o >>= 1) {              // deterministic tree
            if (tid < o) sL1[tid] += sL1[tid + o];
            __syncthreads();
        }
        if (tid == 0) g_l1part[c] = sL1[0];
        __threadfence();
        __syncthreads();
        if (tid == 0) atomicAdd(&g_done, 1);
    }

    // ---- first tile load (non-producers do this while producers compute) ----
    ldg_pass(In, bx, 0, sb, tid);

    // ---- wait for all producers, stage B ----
    if (tid == 0) {
        int v;
        do {
            asm volatile("ld.acquire.gpu.b32 %0, [%1];" : "=r"(v) : "l"(&g_done) : "memory");
            if (v < NPROD) __nanosleep(64);
        } while (v < NPROD);
    }
    __syncthreads();
    {
        const float4* src = (const float4*)g_Bsw;
        float4* dst = (float4*)(dsm + BOF);
#pragma unroll
        for (int k = tid; k < 2048; k += 256) dst[k] = src[k];
    }
    __syncthreads();    // plane0 + rowsums0 + B ready

    const int rA0 = m0 + g;
    const uint32_t bB = sb + BOF + (uint32_t)(n0 + g) * 256;
    const uint32_t xg = (uint32_t)(g << 5);

    const int nt = (NTILES - bx + NCTA - 1) / NCTA;
    float loss = 0.f;

    for (int i = 0; i < nt; ++i) {
        const int tile = bx + i * NCTA;
        const int slot = i & 1;
        const uint32_t pln = sb + (slot ? PLN1 : PLN0);
        const uint32_t bA  = pln + (uint32_t)rA0 * 256;

        // -------- mainloop: bf16 planes, no cvt on hot path --------
        float dacc[2][8][4];
#pragma unroll
        for (int mh = 0; mh < 2; ++mh)
#pragma unroll
            for (int nf = 0; nf < 8; ++nf)
#pragma unroll
                for (int j = 0; j < 4; ++j) dacc[mh][nf][j] = 0.f;

#pragma unroll
        for (int ks = 0; ks < 8; ++ks) {
            const uint32_t off = ((uint32_t)(4 * ks + q) << 3) ^ xg;
            const uint2 r0  = lds64u(bA + off);
            const uint2 r8  = lds64u(bA + 8 * 256 + off);
            const uint2 r16 = lds64u(bA + 16 * 256 + off);
            const uint2 r24 = lds64u(bA + 24 * 256 + off);
            const uint32_t a0[4] = {r0.x,  r8.x,  r0.y,  r8.y};
            const uint32_t a1[4] = {r16.x, r24.x, r16.y, r24.y};
#pragma unroll
            for (int nf = 0; nf < 8; ++nf) {
                const uint2 b = lds64u(bB + (uint32_t)nf * 2048 + off);
                mma_bf16(dacc[0][nf], a0, b.x, b.y);
                mma_bf16(dacc[1][nf], a1, b.x, b.y);
            }
        }

        // -------- epilogue (targets from bf16 plane; rowsums precomputed) --------
        const float* sRow = (const float*)(dsm + ROWS) + slot * 128;
        const size_t base = (size_t)tile * TILE;
#pragma unroll
        for (int mh = 0; mh < 2; ++mh) {
            const int rA = m0 + 16 * mh + g;        // <= 119 (always valid)
            const int rB = rA + 8;                  // <= 127
            const float rsA = sRow[rA];
            const float rsB = sRow[rB];
            const bool vB = (base + rB) < (size_t)(S_LEN - 1);
#pragma unroll
            for (int nf = 0; nf < 8; ++nf) {
                const int col0 = n0 + 8 * nf + 2 * q;     // even
                const uint32_t va = lds32(pln + gsw(rA + 1, col0));
                const float nxa0 = lo_f(va), nxa1 = hi_f(va);
                float nxb0, nxb1;
                if (rB < TILE - 1) {
                    const uint32_t vb = lds32(pln + gsw(rB + 1, col0));
                    nxb0 = lo_f(vb); nxb1 = hi_f(vb);
                } else {
                    const float2 nb = lds64f(sb + NXT + (uint32_t)slot * 512 + col0 * 4);
                    nxb0 = nb.x; nxb1 = nb.y;
                }
                const float* d = dacc[mh][nf];
                const float t0 = fmaf(softplusf(d[0]), rsA, -nxa0);
                const float t1 = fmaf(softplusf(d[1]), rsA, -nxa1);
                loss = fmaf(t0, t0, loss);
                loss = fmaf(t1, t1, loss);
                if (vB) {
                    const float t2 = fmaf(softplusf(d[2]), rsB, -nxb0);
                    const float t3 = fmaf(softplusf(d[3]), rsB, -nxb1);
                    loss = fmaf(t2, t2, loss);
                    loss = fmaf(t3, t3, loss);
                }
            }
        }

        // -------- load next tile into the other plane (no hazard: other buffer) --------
        if (i + 1 < nt) ldg_pass(In, bx + (i + 1) * NCTA, 1 - slot, sb, tid);
        __syncthreads();   // next plane ready; all warps past this iter's reads
    }

    // ---- deterministic CTA reduction ----
    float* sRed = (float*)(dsm + RED);
    sRed[tid] = loss;
    __syncthreads();
#pragma unroll
    for (int o = 128; o; o >>= 1) {
        if (tid < o) sRed[tid] += sRed[tid + o];
        __syncthreads();
    }
    if (tid == 0) g_partials[bx] = sRed[0];

    // ---- last-CTA final reduce (fixed-order => deterministic) ----
    __shared__ int sLast;
    if (tid == 0) {
        __threadfence();
        sLast = (atomicAdd(&g_ticket, 1) == NCTA - 1);
    }
    __syncthreads();
    if (sLast) {
        __threadfence();
        double* dRed = (double*)(dsm + RED);
        double s = 0.0;
        for (int k = tid; k < NCTA; k += 256) s += (double)__ldcg(&g_partials[k]);
        dRed[tid] = s;
        __syncthreads();
        for (int o = 128; o; o >>= 1) {
            if (tid < o) dRed[tid] += dRed[tid + o];
            __syncthreads();
        }
        if (tid == 0)
            out[0] = (float)(dRed[0] / ((double)(S_LEN - 1) * (double)NDIM));
        __syncthreads();

        dRed[tid] = (tid < NPROD) ? (double)__ldcg(&g_l1part[tid]) : 0.0;
        __syncthreads();
        for (int o = 128; o; o >>= 1) {
            if (tid < o) dRed[tid] += dRed[tid + o];
            __syncthreads();
        }
        if (tid == 0) {
            out[1] = (float)dRed[0];
            g_done = 0;                  // reset for next graph replay
            g_ticket = 0;
        }
    }
}

// ---------------- launch ----------------
extern "C" void kernel_launch(void* const* d_in, const int* in_sizes, int n_in,
                              void* d_out, int out_size) {
    const float* In = (const float*)d_in[0];
    const float* WQ = (const float*)d_in[1];
    const float* WK = (const float*)d_in[2];
    float* out = (float*)d_out;

    cudaFuncSetAttribute(fused_kernel,
                         cudaFuncAttributeMaxDynamicSharedMemorySize, SMEM_BYTES);
    fused_kernel<<<NCTA, 256, SMEM_BYTES>>>(In, WQ, WK, out);
}